// round 14
// baseline (speedup 1.0000x reference)
#include <cuda_runtime.h>
#include <cuda_bf16.h>

#define IMAGE 224
#define PAD   30
#define CROP  (IMAGE - 2 * PAD)   // 164
#define NB    16
#define NT    16
#define W4    (IMAGE / 4)         // 56

// One thread handles one (b, c, h, w4-group-of-4). It computes the 4 prompt
// scalars once, then streams the 16 time-steps of x with float4 load+add+store.
// Launch shape = R7 optimum: 2352 blocks x 256, one item/thread (~2.6 waves of
// short blocks — oversubscription beats exact-fit per R11). Single change vs
// R7: __ldcs on the x read stream only (zero reuse -> evict-first frees L2 for
// the dirty write stream + pad tables). Stores keep default policy (store .cs
// regressed in R8).
__global__ __launch_bounds__(256) void prompter_kernel(
    const float* __restrict__ x,
    const float* __restrict__ pu1,  const float* __restrict__ pu10,
    const float* __restrict__ pd1,  const float* __restrict__ pd10,
    const float* __restrict__ pl1,  const float* __restrict__ pl10,
    const float* __restrict__ pr1,  const float* __restrict__ pr10,
    const int*   __restrict__ cam_idx,
    const int*   __restrict__ off_right,
    const int*   __restrict__ off_down,
    float* __restrict__ out)
{
    int idx = blockIdx.x * blockDim.x + threadIdx.x;
    // total = NB*3*IMAGE*W4 = 602112, grid sized exactly
    int w4  = idx % W4;
    int tmp = idx / W4;
    int h   = tmp % IMAGE;
    tmp    /= IMAGE;
    int c   = tmp % 3;
    int b   = tmp / 3;

    const int ci  = __ldg(&cam_idx[b]);
    const int orr = __ldg(&off_right[b]);
    const int od  = __ldg(&off_down[b]);

    const int off_l = 2 * PAD - orr;          // [30, 59]
    const int off_u = 2 * PAD - od;           // [30, 59]
    const int n10_l = off_l / 10;
    const int n10_u = off_u / 10;
    const int n1_r  = orr % 10;
    const int n1_d  = od % 10;

    const int cc = ci * 3 + c;

    // Row-level (h-dependent) precompute
    const int hd = h - (IMAGE - od);
    int di = hd - n1_d;                        // >= 0 whenever the pd10 branch is taken
    di = ((di % 10) + 10) % 10;
    int r = h - off_u;
    r = min(max(r, 0), CROP - 1);

    const float* pu1_row  = pu1  + cc * IMAGE;
    const float* pu10_row = pu10 + (cc * 10 + (h % 10)) * IMAGE;
    const float* pd1_row  = pd1  + cc * IMAGE;
    const float* pd10_row = pd10 + (cc * 10 + di) * IMAGE;
    const float  pl1_v    = pl1[cc * CROP + r];
    const float* pl10_row = pl10 + (cc * CROP + r) * 10;
    const float  pr1_v    = pr1[cc * CROP + r];
    const float* pr10_row = pr10 + (cc * CROP + r) * 10;

    const int w0 = w4 * 4;
    float pv[4];
#pragma unroll
    for (int j = 0; j < 4; ++j) {
        const int w = w0 + j;
        float v;
        if (h < off_u) {
            // top band
            v = (h < n10_u * 10) ? pu10_row[w] : pu1_row[w];
        } else if (h >= IMAGE - od) {
            // bottom band
            v = (hd < n1_d) ? pd1_row[w] : pd10_row[w];
        } else {
            // middle rows: left band / right band / interior zero
            if (w < off_l) {
                v = (w < n10_l * 10) ? pl10_row[w % 10] : pl1_v;
            } else if (w >= IMAGE - orr) {
                const int wd = w - (IMAGE - orr);
                int ri = wd - n1_r;            // >= 0 whenever pr10 branch taken
                ri = ((ri % 10) + 10) % 10;
                v = (wd < n1_r) ? pr1_v : pr10_row[ri];
            } else {
                v = 0.0f;
            }
        }
        pv[j] = v;
    }

    // Stream the 16 time-steps: base (b, c, t=0, h, w0), stride IMAGE*IMAGE per t
    const long base = (long)(b * 3 + c) * (NT * IMAGE * IMAGE) + h * IMAGE + w0;
    const float4* __restrict__ xin = reinterpret_cast<const float4*>(x + base);
    float4* __restrict__ xo        = reinterpret_cast<float4*>(out + base);
    const int stride4 = IMAGE * IMAGE / 4;     // 12544 float4 per t

#pragma unroll
    for (int t = 0; t < NT; ++t) {
        float4 v = __ldcs(&xin[t * stride4]);   // evict-first READ only (zero reuse)
        v.x += pv[0];
        v.y += pv[1];
        v.z += pv[2];
        v.w += pv[3];
        xo[t * stride4] = v;                    // default store policy (R7)
    }
}

extern "C" void kernel_launch(void* const* d_in, const int* in_sizes, int n_in,
                              void* d_out, int out_size) {
    // metadata order:
    // 0: x            (16,3,16,224,224) f32
    // 1: pad_up_1     (3,3,1,224)       f32
    // 2: pad_up_10    (3,3,10,224)      f32
    // 3: pad_down_1   (3,3,1,224)       f32
    // 4: pad_down_10  (3,3,10,224)      f32
    // 5: pad_left_1   (3,3,164,1)       f32
    // 6: pad_left_10  (3,3,164,10)      f32
    // 7: pad_right_1  (3,3,164,1)       f32
    // 8: pad_right_10 (3,3,164,10)      f32
    // 9: cam_idx      (16,)             i32
    // 10: off_right   (16,)             i32
    // 11: off_down    (16,)             i32
    const float* x    = (const float*)d_in[0];
    const float* pu1  = (const float*)d_in[1];
    const float* pu10 = (const float*)d_in[2];
    const float* pd1  = (const float*)d_in[3];
    const float* pd10 = (const float*)d_in[4];
    const float* pl1  = (const float*)d_in[5];
    const float* pl10 = (const float*)d_in[6];
    const float* pr1  = (const float*)d_in[7];
    const float* pr10 = (const float*)d_in[8];
    const int* cam_idx   = (const int*)d_in[9];
    const int* off_right = (const int*)d_in[10];
    const int* off_down  = (const int*)d_in[11];
    float* out = (float*)d_out;

    const int total  = NB * 3 * IMAGE * W4;   // 602112
    const int block  = 256;
    const int grid   = total / block;          // 2352, exact
    prompter_kernel<<<grid, block>>>(x, pu1, pu10, pd1, pd10, pl1, pl10,
                                     pr1, pr10, cam_idx, off_right, off_down,
                                     out);
}

// round 15
// speedup vs baseline: 1.1554x; 1.1554x over previous
#include <cuda_runtime.h>
#include <cuda_bf16.h>

#define IMAGE 224
#define PAD   30
#define CROP  (IMAGE - 2 * PAD)   // 164
#define NB    16
#define NT    16
#define W4    (IMAGE / 4)         // 56

// One thread handles one (b, c, h, w4-group-of-4). It computes the 4 prompt
// scalars once, then streams the 16 time-steps of x with float4 load+add+store.
// Pad tables are tiny (<200 KB) and L2/L1 resident; x/out traffic (~308 MB)
// is the roofline.
//
// PINNED CONFIG (R7): 2352 blocks x 256 threads, one item/thread, DEFAULT
// cache policy on both streams. Measured 44.48us kernel = 6.93 TB/s = 87% of
// HBM spec. Experiments proven NEGATIVE on sm_103a, do not retry:
//   - __stcs / __ldcs on the streams (R8, R14): each costs ~6-7us kernel time
//   - exact-fit single-wave grid (784x256, 3 items/thread) (R11): -8us
//   - block=512 (R8): regression
__global__ __launch_bounds__(256) void prompter_kernel(
    const float* __restrict__ x,
    const float* __restrict__ pu1,  const float* __restrict__ pu10,
    const float* __restrict__ pd1,  const float* __restrict__ pd10,
    const float* __restrict__ pl1,  const float* __restrict__ pl10,
    const float* __restrict__ pr1,  const float* __restrict__ pr10,
    const int*   __restrict__ cam_idx,
    const int*   __restrict__ off_right,
    const int*   __restrict__ off_down,
    float* __restrict__ out)
{
    int idx = blockIdx.x * blockDim.x + threadIdx.x;
    // total = NB*3*IMAGE*W4 = 602112, grid sized exactly
    int w4  = idx % W4;
    int tmp = idx / W4;
    int h   = tmp % IMAGE;
    tmp    /= IMAGE;
    int c   = tmp % 3;
    int b   = tmp / 3;

    const int ci  = __ldg(&cam_idx[b]);
    const int orr = __ldg(&off_right[b]);
    const int od  = __ldg(&off_down[b]);

    const int off_l = 2 * PAD - orr;          // [30, 59]
    const int off_u = 2 * PAD - od;           // [30, 59]
    const int n10_l = off_l / 10;
    const int n10_u = off_u / 10;
    const int n1_r  = orr % 10;
    const int n1_d  = od % 10;

    const int cc = ci * 3 + c;

    // Row-level (h-dependent) precompute
    const int hd = h - (IMAGE - od);
    int di = hd - n1_d;                        // >= 0 whenever the pd10 branch is taken
    di = ((di % 10) + 10) % 10;
    int r = h - off_u;
    r = min(max(r, 0), CROP - 1);

    const float* pu1_row  = pu1  + cc * IMAGE;
    const float* pu10_row = pu10 + (cc * 10 + (h % 10)) * IMAGE;
    const float* pd1_row  = pd1  + cc * IMAGE;
    const float* pd10_row = pd10 + (cc * 10 + di) * IMAGE;
    const float  pl1_v    = pl1[cc * CROP + r];
    const float* pl10_row = pl10 + (cc * CROP + r) * 10;
    const float  pr1_v    = pr1[cc * CROP + r];
    const float* pr10_row = pr10 + (cc * CROP + r) * 10;

    const int w0 = w4 * 4;
    float pv[4];
#pragma unroll
    for (int j = 0; j < 4; ++j) {
        const int w = w0 + j;
        float v;
        if (h < off_u) {
            // top band
            v = (h < n10_u * 10) ? pu10_row[w] : pu1_row[w];
        } else if (h >= IMAGE - od) {
            // bottom band
            v = (hd < n1_d) ? pd1_row[w] : pd10_row[w];
        } else {
            // middle rows: left band / right band / interior zero
            if (w < off_l) {
                v = (w < n10_l * 10) ? pl10_row[w % 10] : pl1_v;
            } else if (w >= IMAGE - orr) {
                const int wd = w - (IMAGE - orr);
                int ri = wd - n1_r;            // >= 0 whenever pr10 branch taken
                ri = ((ri % 10) + 10) % 10;
                v = (wd < n1_r) ? pr1_v : pr10_row[ri];
            } else {
                v = 0.0f;
            }
        }
        pv[j] = v;
    }

    // Stream the 16 time-steps: base (b, c, t=0, h, w0), stride IMAGE*IMAGE per t
    const long base = (long)(b * 3 + c) * (NT * IMAGE * IMAGE) + h * IMAGE + w0;
    const float4* __restrict__ xin = reinterpret_cast<const float4*>(x + base);
    float4* __restrict__ xo        = reinterpret_cast<float4*>(out + base);
    const int stride4 = IMAGE * IMAGE / 4;     // 12544 float4 per t

#pragma unroll
    for (int t = 0; t < NT; ++t) {
        float4 v = xin[t * stride4];
        v.x += pv[0];
        v.y += pv[1];
        v.z += pv[2];
        v.w += pv[3];
        xo[t * stride4] = v;
    }
}

extern "C" void kernel_launch(void* const* d_in, const int* in_sizes, int n_in,
                              void* d_out, int out_size) {
    // metadata order:
    // 0: x            (16,3,16,224,224) f32
    // 1: pad_up_1     (3,3,1,224)       f32
    // 2: pad_up_10    (3,3,10,224)      f32
    // 3: pad_down_1   (3,3,1,224)       f32
    // 4: pad_down_10  (3,3,10,224)      f32
    // 5: pad_left_1   (3,3,164,1)       f32
    // 6: pad_left_10  (3,3,164,10)      f32
    // 7: pad_right_1  (3,3,164,1)       f32
    // 8: pad_right_10 (3,3,164,10)      f32
    // 9: cam_idx      (16,)             i32
    // 10: off_right   (16,)             i32
    // 11: off_down    (16,)             i32
    const float* x    = (const float*)d_in[0];
    const float* pu1  = (const float*)d_in[1];
    const float* pu10 = (const float*)d_in[2];
    const float* pd1  = (const float*)d_in[3];
    const float* pd10 = (const float*)d_in[4];
    const float* pl1  = (const float*)d_in[5];
    const float* pl10 = (const float*)d_in[6];
    const float* pr1  = (const float*)d_in[7];
    const float* pr10 = (const float*)d_in[8];
    const int* cam_idx   = (const int*)d_in[9];
    const int* off_right = (const int*)d_in[10];
    const int* off_down  = (const int*)d_in[11];
    float* out = (float*)d_out;

    const int total  = NB * 3 * IMAGE * W4;   // 602112
    const int block  = 256;
    const int grid   = total / block;          // 2352, exact
    prompter_kernel<<<grid, block>>>(x, pu1, pu10, pd1, pd10, pl1, pl10,
                                     pr1, pr10, cam_idx, off_right, off_down,
                                     out);
}